// round 2
// baseline (speedup 1.0000x reference)
#include <cuda_runtime.h>

#define BB 2
#define TT 2048
#define HH 16
#define DD 64
#define DM 1024
#define MROWS (BB*TT)   // 4096

// Scratch (no cudaMalloc allowed) — ~34MB static device memory.
__device__ float g_q[BB*TT*DM];     // Q projection output [B,T,H*D]
__device__ float g_k[BB*TT*DD];     // K projection output [B,T,D]
__device__ float g_v[BB*TT*DD];     // V projection output [B,T,D]
__device__ float g_attn[BB*TT*DM];  // attention output    [B,T,H*D]

// ---------------------------------------------------------------------------
// Generic SGEMM with bias: C[M,N] = A[M,K] @ W[K,N] + bias[N]
// BM=BN=64, BK=16, 256 threads, 4x4 register tile per thread.
// Requires M%64==0, N%64==0, K%16==0 (all true here).
// ---------------------------------------------------------------------------
__global__ __launch_bounds__(256) void sgemm_bias(
    const float* __restrict__ A, const float* __restrict__ W,
    const float* __restrict__ bias, float* __restrict__ C,
    int M, int N, int K)
{
    __shared__ float As[16][64];   // As[k][m] (A transposed in smem)
    __shared__ float Ws[16][64];   // Ws[k][n]

    const int tid = threadIdx.x;
    const int tx = tid & 15;       // 16 column groups
    const int ty = tid >> 4;       // 16 row groups
    const int bm = blockIdx.y * 64;
    const int bn = blockIdx.x * 64;

    const int arow = tid >> 2;           // 0..63
    const int acol = (tid & 3) << 2;     // 0,4,8,12
    const int wrow = tid >> 4;           // 0..15
    const int wcol = (tid & 15) << 2;    // 0..60

    float acc[4][4] = {};

    for (int k0 = 0; k0 < K; k0 += 16) {
        float4 a = *(const float4*)(A + (size_t)(bm + arow) * K + k0 + acol);
        As[acol + 0][arow] = a.x;
        As[acol + 1][arow] = a.y;
        As[acol + 2][arow] = a.z;
        As[acol + 3][arow] = a.w;
        *(float4*)&Ws[wrow][wcol] =
            *(const float4*)(W + (size_t)(k0 + wrow) * N + bn + wcol);
        __syncthreads();

        #pragma unroll
        for (int kk = 0; kk < 16; kk++) {
            float4 av = *(const float4*)&As[kk][ty << 2];
            float4 wv = *(const float4*)&Ws[kk][tx << 2];
            float am[4] = {av.x, av.y, av.z, av.w};
            float wm[4] = {wv.x, wv.y, wv.z, wv.w};
            #pragma unroll
            for (int j = 0; j < 4; j++)
                #pragma unroll
                for (int i = 0; i < 4; i++)
                    acc[j][i] += am[j] * wm[i];
        }
        __syncthreads();
    }

    #pragma unroll
    for (int j = 0; j < 4; j++) {
        const int r = bm + (ty << 2) + j;
        const int c = bn + (tx << 2);
        float4 o;
        o.x = acc[j][0] + bias[c + 0];
        o.y = acc[j][1] + bias[c + 1];
        o.z = acc[j][2] + bias[c + 2];
        o.w = acc[j][3] + bias[c + 3];
        *(float4*)(C + (size_t)r * N + c) = o;
    }
}

// ---------------------------------------------------------------------------
// Flash-attention (MQA): per block one (b, h, 64 q-rows) tile.
// Streams K/V in 64-key chunks through SMEM with online softmax.
// K stored d-major (transposed) in SMEM to keep S-GEMM loads vectorized.
// 256 threads, 4x4 tiles. Dynamic SMEM: 4 * 64*68 floats = 69632 B.
// ---------------------------------------------------------------------------
#define PAD 68

__global__ __launch_bounds__(256) void mqa_attn(
    const float* __restrict__ q, const float* __restrict__ k,
    const float* __restrict__ v, float* __restrict__ out)
{
    extern __shared__ float smem[];
    float* Qs = smem;               // [64][PAD] row-major (q rows, scaled)
    float* Kt = Qs + 64 * PAD;      // [64][PAD] d-major: Kt[d][key]
    float* Vs = Kt + 64 * PAD;      // [64][PAD] row-major: Vs[key][d]
    float* Ps = Vs + 64 * PAD;      // [64][PAD] row-major: Ps[qrow][key]

    const int tid = threadIdx.x;
    const int tx = tid & 15;
    const int ty = tid >> 4;

    const int bi = blockIdx.x;
    const int qt = bi & 31;          // T/64 = 32 q tiles
    const int h  = (bi >> 5) & 15;
    const int b  = bi >> 9;

    const int qbase  = b * TT + qt * 64;   // global q-row base
    const int kvbase = b * TT;             // global key base

    // Load Q tile, pre-scaled by 1/sqrt(64) = 0.125
    for (int idx = tid; idx < 64 * 16; idx += 256) {
        const int r  = idx >> 4;
        const int d4 = (idx & 15) << 2;
        float4 val = *(const float4*)(q + (size_t)(qbase + r) * DM + h * DD + d4);
        val.x *= 0.125f; val.y *= 0.125f; val.z *= 0.125f; val.w *= 0.125f;
        *(float4*)&Qs[r * PAD + d4] = val;
    }

    float m[4], l[4], acc[4][4];
    #pragma unroll
    for (int j = 0; j < 4; j++) {
        m[j] = -1e30f; l[j] = 0.f;
        #pragma unroll
        for (int i = 0; i < 4; i++) acc[j][i] = 0.f;
    }

    for (int kc = 0; kc < TT; kc += 64) {
        __syncthreads();   // prior iteration done reading Kt/Vs/Ps (and Qs on iter 0)

        // Load K chunk (transposed into Kt) and V chunk (row-major).
        // Mapping: 32 consecutive lanes -> 32 consecutive keys, same d4
        // => conflict-free Kt scalar stores (bank = key % 32, all distinct).
        for (int idx = tid; idx < 64 * 16; idx += 256) {
            const int row = idx & 63;          // key within chunk
            const int d4  = (idx >> 6) << 2;   // 0,4,...,60
            float4 kv = *(const float4*)(k + (size_t)(kvbase + kc + row) * DD + d4);
            Kt[(d4 + 0) * PAD + row] = kv.x;
            Kt[(d4 + 1) * PAD + row] = kv.y;
            Kt[(d4 + 2) * PAD + row] = kv.z;
            Kt[(d4 + 3) * PAD + row] = kv.w;
            float4 vv = *(const float4*)(v + (size_t)(kvbase + kc + row) * DD + d4);
            *(float4*)&Vs[row * PAD + d4] = vv;
        }
        __syncthreads();

        // S[j][i] = sum_d Qs[r_j][d] * K[c_i][d], r_j = ty*4+j, c_i = tx*4+i
        float s[4][4] = {};
        #pragma unroll
        for (int d4 = 0; d4 < 64; d4 += 4) {
            const float4 kt0 = *(const float4*)&Kt[(d4 + 0) * PAD + (tx << 2)];
            const float4 kt1 = *(const float4*)&Kt[(d4 + 1) * PAD + (tx << 2)];
            const float4 kt2 = *(const float4*)&Kt[(d4 + 2) * PAD + (tx << 2)];
            const float4 kt3 = *(const float4*)&Kt[(d4 + 3) * PAD + (tx << 2)];
            #pragma unroll
            for (int j = 0; j < 4; j++) {
                const float4 qv = *(const float4*)&Qs[((ty << 2) + j) * PAD + d4];
                s[j][0] += qv.x * kt0.x + qv.y * kt1.x + qv.z * kt2.x + qv.w * kt3.x;
                s[j][1] += qv.x * kt0.y + qv.y * kt1.y + qv.z * kt2.y + qv.w * kt3.y;
                s[j][2] += qv.x * kt0.z + qv.y * kt1.z + qv.z * kt2.z + qv.w * kt3.z;
                s[j][3] += qv.x * kt0.w + qv.y * kt1.w + qv.z * kt2.w + qv.w * kt3.w;
            }
        }

        // Online softmax. Row owned by the 16 lanes with equal ty
        // (contiguous 16-lane subsegments -> shfl width 16).
        #pragma unroll
        for (int j = 0; j < 4; j++) {
            float mx = fmaxf(fmaxf(s[j][0], s[j][1]), fmaxf(s[j][2], s[j][3]));
            #pragma unroll
            for (int o = 8; o > 0; o >>= 1)
                mx = fmaxf(mx, __shfl_xor_sync(0xffffffffu, mx, o, 16));
            const float mn = fmaxf(m[j], mx);
            const float alpha = __expf(m[j] - mn);
            float ls = 0.f;
            #pragma unroll
            for (int i = 0; i < 4; i++) { s[j][i] = __expf(s[j][i] - mn); ls += s[j][i]; }
            #pragma unroll
            for (int o = 8; o > 0; o >>= 1)
                ls += __shfl_xor_sync(0xffffffffu, ls, o, 16);
            l[j] = l[j] * alpha + ls;
            m[j] = mn;
            #pragma unroll
            for (int i = 0; i < 4; i++) acc[j][i] *= alpha;
            *(float4*)&Ps[((ty << 2) + j) * PAD + (tx << 2)] =
                make_float4(s[j][0], s[j][1], s[j][2], s[j][3]);
        }
        __syncthreads();

        // acc[j][i] += sum_k Ps[r_j][k] * Vs[k][dc_i], dc_i = tx*4+i
        #pragma unroll
        for (int k4 = 0; k4 < 64; k4 += 4) {
            const float4 vv0 = *(const float4*)&Vs[(k4 + 0) * PAD + (tx << 2)];
            const float4 vv1 = *(const float4*)&Vs[(k4 + 1) * PAD + (tx << 2)];
            const float4 vv2 = *(const float4*)&Vs[(k4 + 2) * PAD + (tx << 2)];
            const float4 vv3 = *(const float4*)&Vs[(k4 + 3) * PAD + (tx << 2)];
            #pragma unroll
            for (int j = 0; j < 4; j++) {
                const float4 pv = *(const float4*)&Ps[((ty << 2) + j) * PAD + k4];
                acc[j][0] += pv.x * vv0.x + pv.y * vv1.x + pv.z * vv2.x + pv.w * vv3.x;
                acc[j][1] += pv.x * vv0.y + pv.y * vv1.y + pv.z * vv2.y + pv.w * vv3.y;
                acc[j][2] += pv.x * vv0.z + pv.y * vv1.z + pv.z * vv2.z + pv.w * vv3.z;
                acc[j][3] += pv.x * vv0.w + pv.y * vv1.w + pv.z * vv2.w + pv.w * vv3.w;
            }
        }
    }

    // Normalize and write out[b, qrow, h*64 + dc]
    #pragma unroll
    for (int j = 0; j < 4; j++) {
        const float inv = 1.f / l[j];
        const int r = qbase + (ty << 2) + j;
        float4 o = make_float4(acc[j][0] * inv, acc[j][1] * inv,
                               acc[j][2] * inv, acc[j][3] * inv);
        *(float4*)(out + (size_t)r * DM + h * DD + (tx << 2)) = o;
    }
}

// ---------------------------------------------------------------------------
extern "C" void kernel_launch(void* const* d_in, const int* in_sizes, int n_in,
                              void* d_out, int out_size)
{
    const float* query = (const float*)d_in[0];
    const float* Wq    = (const float*)d_in[1];
    const float* bq    = (const float*)d_in[2];
    const float* Wk    = (const float*)d_in[3];
    const float* bk    = (const float*)d_in[4];
    const float* Wv    = (const float*)d_in[5];
    const float* bv    = (const float*)d_in[6];
    const float* Wo    = (const float*)d_in[7];
    const float* bo    = (const float*)d_in[8];
    float* out = (float*)d_out;

    float *qb, *kb, *vb, *ab;
    cudaGetSymbolAddress((void**)&qb, g_q);
    cudaGetSymbolAddress((void**)&kb, g_k);
    cudaGetSymbolAddress((void**)&vb, g_v);
    cudaGetSymbolAddress((void**)&ab, g_attn);

    const size_t attn_smem = 4 * 64 * PAD * sizeof(float);  // 69632 B
    cudaFuncSetAttribute(mqa_attn, cudaFuncAttributeMaxDynamicSharedMemorySize,
                         (int)attn_smem);

    // K, V, Q projections
    sgemm_bias<<<dim3(1, 64),  256>>>(query, Wk, bk, kb, MROWS, DD, DM);
    sgemm_bias<<<dim3(1, 64),  256>>>(query, Wv, bv, vb, MROWS, DD, DM);
    sgemm_bias<<<dim3(16, 64), 256>>>(query, Wq, bq, qb, MROWS, DM, DM);

    // Attention: B * H * (T/64) = 1024 blocks
    mqa_attn<<<1024, 256, attn_smem>>>(qb, kb, vb, ab);

    // Output projection -> d_out
    sgemm_bias<<<dim3(16, 64), 256>>>(ab, Wo, bo, out, MROWS, DM, DM);
}

// round 6
// speedup vs baseline: 1.6330x; 1.6330x over previous
#include <cuda_runtime.h>
#include <cstdint>

#define TT 2048
#define DM 1024
#define MROWS 4096

// Scratch (no cudaMalloc allowed)
__device__ float g_q[MROWS*DM];
__device__ float g_k[MROWS*64];
__device__ float g_v[MROWS*64];
__device__ float g_attn[MROWS*DM];

static __device__ __forceinline__ uint32_t f2tf32(float x){
    uint32_t u; asm("cvt.rn.tf32.f32 %0, %1;" : "=r"(u) : "f"(x)); return u;
}
// D += A(m16k8 row) * B(k8n8 col), tf32 inputs, f32 accum
static __device__ __forceinline__ void mma8(float* c, const uint32_t* a, const uint32_t* b){
    asm volatile("mma.sync.aligned.m16n8k8.row.col.f32.tf32.tf32.f32 "
        "{%0,%1,%2,%3}, {%4,%5,%6,%7}, {%8,%9}, {%0,%1,%2,%3};"
        : "+f"(c[0]),"+f"(c[1]),"+f"(c[2]),"+f"(c[3])
        : "r"(a[0]),"r"(a[1]),"r"(a[2]),"r"(a[3]), "r"(b[0]),"r"(b[1]));
}

// ---------------------------------------------------------------------------
// tf32 mma.sync GEMM + bias: C[M,N] = A[M,K] @ W[K,N] + bias
// Block tile 128 x NT, BK=16, 256 threads, warp grid 2x4, warp tile 64 x NT/4.
// SMEM staged in fragment-shuffled layout:
//   A-frag tile (16x8): 32 lanes x 4 floats contiguous (lane = g*4+t holds
//     {A[g][t], A[g+8][t], A[g][t+4], A[g+8][t+4]})
//   B-frag tile (8x8):  32 lanes x 2 floats (lane = n*4+(k&3) holds
//     {B[k&3][n], B[(k&3)+4][n]})
// ---------------------------------------------------------------------------
template<int NT>
__global__ __launch_bounds__(256, 2) void gemm_mma(
    const float* __restrict__ A, const float* __restrict__ W,
    const float* __restrict__ bias, float* __restrict__ C,
    int M, int N, int K)
{
    extern __shared__ char smem[];
    constexpr int WNT  = NT / 32;     // n-tiles per warp (4 or 2)
    constexpr int BBUF = NT * 64;     // bytes per B buffer
    constexpr int NBF4 = NT / 64;     // B float4 loads per thread (2 or 1)

    const int tid = threadIdx.x, lane = tid & 31, wid = tid >> 5;
    const int wm = wid >> 2, wn = wid & 3;
    const int bm = blockIdx.y * 128, bn = blockIdx.x * NT;
    const int NC = K >> 4;

    float4 ar[2], br[2];
    auto ldg = [&](int c){
        const int k0 = c << 4;
        #pragma unroll
        for (int i = 0; i < 2; i++){
            int idx = tid + (i << 8); int r = idx >> 2, c4 = (idx & 3) << 2;
            ar[i] = *(const float4*)(A + (size_t)(bm + r) * K + k0 + c4);
        }
        #pragma unroll
        for (int i = 0; i < NBF4; i++){
            int idx = tid + (i << 8); int kk = idx / (NT >> 2), n4 = (idx % (NT >> 2)) << 2;
            br[i] = *(const float4*)(W + (size_t)(k0 + kk) * N + bn + n4);
        }
    };
    auto sts = [&](int buf){
        char* as = smem + buf * 8192;
        char* bs = smem + 16384 + buf * BBUF;
        #pragma unroll
        for (int i = 0; i < 2; i++){
            int idx = tid + (i << 8); int r = idx >> 2, c4 = (idx & 3) << 2;
            int mt = r >> 4, rr = r & 15, g = rr & 7, hi = rr >> 3;
            float v[4] = {ar[i].x, ar[i].y, ar[i].z, ar[i].w};
            #pragma unroll
            for (int j = 0; j < 4; j++){
                int cc = c4 + j, ks = cc >> 3, c7 = cc & 7, t = c7 & 3, chi = c7 >> 2;
                *(uint32_t*)(as + (((mt*2 + ks) << 7) + ((g << 2) + t) * 4 + hi + (chi << 1)) * 4)
                    = f2tf32(v[j]);
            }
        }
        #pragma unroll
        for (int i = 0; i < NBF4; i++){
            int idx = tid + (i << 8); int kk = idx / (NT >> 2), n4 = (idx % (NT >> 2)) << 2;
            int ks = kk >> 3, k7 = kk & 7, slot = k7 >> 2, kb = k7 & 3;
            float v[4] = {br[i].x, br[i].y, br[i].z, br[i].w};
            #pragma unroll
            for (int j = 0; j < 4; j++){
                int n = n4 + j, nt = n >> 3;
                *(uint32_t*)(bs + (((nt*2 + ks) << 6) + (((n & 7) << 2) + kb) * 2 + slot) * 4)
                    = f2tf32(v[j]);
            }
        }
    };

    float acc[4][WNT][4] = {};
    auto comp = [&](int buf){
        const char* as = smem + buf * 8192;
        const char* bs = smem + 16384 + buf * BBUF;
        #pragma unroll
        for (int ks = 0; ks < 2; ks++){
            uint4 af[4]; uint2 bf[WNT];
            #pragma unroll
            for (int mt = 0; mt < 4; mt++)
                af[mt] = *(const uint4*)(as + ((((wm*4 + mt)*2 + ks) << 9)) + (lane << 4));
            #pragma unroll
            for (int nt = 0; nt < WNT; nt++)
                bf[nt] = *(const uint2*)(bs + ((((wn*WNT + nt)*2 + ks) << 8)) + (lane << 3));
            #pragma unroll
            for (int mt = 0; mt < 4; mt++)
                #pragma unroll
                for (int nt = 0; nt < WNT; nt++)
                    mma8(acc[mt][nt], (const uint32_t*)&af[mt], (const uint32_t*)&bf[nt]);
        }
    };

    ldg(0); sts(0); __syncthreads();
    for (int c = 0; c < NC; c++){
        if (c + 1 < NC) ldg(c + 1);
        comp(c & 1);
        if (c + 1 < NC) sts((c + 1) & 1);
        __syncthreads();
    }

    const int g = lane >> 2, tt = lane & 3;
    #pragma unroll
    for (int mt = 0; mt < 4; mt++){
        int row = bm + wm*64 + mt*16 + g;
        #pragma unroll
        for (int nt = 0; nt < WNT; nt++){
            int col = bn + (wn*WNT + nt)*8 + (tt << 1);
            float b0 = bias[col], b1 = bias[col + 1];
            *(float2*)(C + (size_t)row * N + col) =
                make_float2(acc[mt][nt][0] + b0, acc[mt][nt][1] + b1);
            *(float2*)(C + (size_t)(row + 8) * N + col) =
                make_float2(acc[mt][nt][2] + b0, acc[mt][nt][3] + b1);
        }
    }
}

// ---------------------------------------------------------------------------
// mma.sync flash-MQA: one block = (b, h, 128 q-rows), 64-key chunks.
// GEMM1: S = Q*K^T (frags in regs) -> exp (no max; scores bounded) ->
// P via SMEM (A-frag layout) -> GEMM2: O += P*V in fp32 registers.
// Unnormalized accumulation; divide by row-sum l at the end.
// SMEM: QF 32K | KF 16K | VF 16K | PF 32K | LS 2K  = 98K -> 2 CTA/SM.
// ---------------------------------------------------------------------------
__global__ __launch_bounds__(256, 2) void attn_mma(
    const float* __restrict__ q, const float* __restrict__ k,
    const float* __restrict__ v, float* __restrict__ out)
{
    extern __shared__ char smem[];
    char* QF = smem;                      // 32768: [8 mt][8 ks] A-frag tiles
    char* KF = smem + 32768;              // 16384: [8 nt(key)][8 kt(d)] B-frag
    char* VF = smem + 49152;              // 16384: [8 nt(d)][8 kt(key)] B-frag
    char* PF = smem + 65536;              // 32768: [8 mt][8 ks(key)] A-frag
    float* LS = (float*)(smem + 98304);   // [128 rows][4 wn]

    const int tid = threadIdx.x, lane = tid & 31, wid = tid >> 5;
    const int wm = wid >> 2, wn = wid & 3;
    const int g = lane >> 2, tt = lane & 3;
    const int bi = blockIdx.x;
    const int qt = bi & 15, h = (bi >> 4) & 15, b = bi >> 8;
    const int qbase = b * TT + qt * 128, kvbase = b * TT;

    // Stage Q (pre-scaled by 1/8) into A-frag layout
    #pragma unroll
    for (int i = 0; i < 8; i++){
        int idx = tid + (i << 8); int r = idx >> 4, d4 = (idx & 15) << 2;
        float4 a = *(const float4*)(q + (size_t)(qbase + r) * DM + h*64 + d4);
        int mt = r >> 4, rr = r & 15, gg = rr & 7, hi = rr >> 3;
        float vv[4] = {a.x, a.y, a.z, a.w};
        #pragma unroll
        for (int j = 0; j < 4; j++){
            int c = d4 + j, ks = c >> 3, c7 = c & 7, t = c7 & 3, chi = c7 >> 2;
            *(uint32_t*)(QF + (((mt*8 + ks) << 7) + ((gg << 2) + t) * 4 + hi + (chi << 1)) * 4)
                = f2tf32(vv[j] * 0.125f);
        }
    }

    float4 kr[4], vr[4];
    auto ldg_kv = [&](int c){
        const int kc = c << 6;
        #pragma unroll
        for (int i = 0; i < 4; i++){
            int idx = tid + (i << 8); int key = idx >> 4, d4 = (idx & 15) << 2;
            kr[i] = *(const float4*)(k + (size_t)(kvbase + kc + key) * 64 + d4);
            vr[i] = *(const float4*)(v + (size_t)(kvbase + kc + key) * 64 + d4);
        }
    };
    auto sts_kv = [&](){
        #pragma unroll
        for (int i = 0; i < 4; i++){
            int idx = tid + (i << 8); int key = idx >> 4, d4 = (idx & 15) << 2;
            float kk4[4] = {kr[i].x, kr[i].y, kr[i].z, kr[i].w};
            float vv4[4] = {vr[i].x, vr[i].y, vr[i].z, vr[i].w};
            #pragma unroll
            for (int j = 0; j < 4; j++){
                int d = d4 + j;
                // K as B[k=d][n=key]:  tile=(key>>3)*8+(d>>3), lane=(key&7)*4+(d&3), slot=(d&7)>>2
                *(uint32_t*)(KF + ((((key >> 3)*8 + (d >> 3)) << 6)
                    + (((key & 7) << 2) + (d & 3)) * 2 + ((d & 7) >> 2)) * 4) = f2tf32(kk4[j]);
                // V as B[k=key][n=d]:  tile=(d>>3)*8+(key>>3), lane=(d&7)*4+(key&3), slot=(key&7)>>2
                *(uint32_t*)(VF + ((((d >> 3)*8 + (key >> 3)) << 6)
                    + (((d & 7) << 2) + (key & 3)) * 2 + ((key & 7) >> 2)) * 4) = f2tf32(vv4[j]);
            }
        }
    };

    float o[4][2][4] = {};
    float l0[4] = {}, l1[4] = {};

    ldg_kv(0); sts_kv(); __syncthreads();

    for (int c = 0; c < 32; c++){
        // GEMM1: S = Q * K^T  (warp tile: m 64, n 16 keys)
        float s[4][2][4] = {};
        #pragma unroll
        for (int ks = 0; ks < 8; ks++){
            uint4 af[4]; uint2 bf[2];
            #pragma unroll
            for (int mt = 0; mt < 4; mt++)
                af[mt] = *(const uint4*)(QF + ((((wm*4 + mt)*8 + ks) << 9)) + (lane << 4));
            #pragma unroll
            for (int nt = 0; nt < 2; nt++)
                bf[nt] = *(const uint2*)(KF + ((((wn*2 + nt)*8 + ks) << 8)) + (lane << 3));
            #pragma unroll
            for (int mt = 0; mt < 4; mt++)
                #pragma unroll
                for (int nt = 0; nt < 2; nt++)
                    mma8(s[mt][nt], (const uint32_t*)&af[mt], (const uint32_t*)&bf[nt]);
        }

        // exp (tf32-rounded so l matches GEMM2 exactly) + row-sum accumulation
        #pragma unroll
        for (int mt = 0; mt < 4; mt++){
            float rs0 = 0.f, rs1 = 0.f;
            #pragma unroll
            for (int nt = 0; nt < 2; nt++){
                #pragma unroll
                for (int e = 0; e < 4; e++){
                    float p = __uint_as_float(f2tf32(__expf(s[mt][nt][e])));
                    s[mt][nt][e] = p;
                    if (e < 2) rs0 += p; else rs1 += p;
                }
            }
            rs0 += __shfl_xor_sync(~0u, rs0, 1); rs0 += __shfl_xor_sync(~0u, rs0, 2);
            rs1 += __shfl_xor_sync(~0u, rs1, 1); rs1 += __shfl_xor_sync(~0u, rs1, 2);
            l0[mt] += rs0; l1[mt] += rs1;
        }

        __syncthreads();   // GEMM2(c-1) finished everywhere -> PF writable

        // Store P into A-frag layout (C-frag cols 2t,2t+1 -> A-frag lanes/slots)
        #pragma unroll
        for (int mt = 0; mt < 4; mt++)
            #pragma unroll
            for (int nt = 0; nt < 2; nt++){
                char* base = PF + (((wm*4 + mt)*8 + wn*2 + nt) << 9);
                int kk0 = tt << 1, kk1 = kk0 + 1;
                uint2* p0 = (uint2*)(base + (((g << 2) + (kk0 & 3)) * 4 + ((kk0 >> 2) << 1)) * 4);
                *p0 = make_uint2(__float_as_uint(s[mt][nt][0]), __float_as_uint(s[mt][nt][2]));
                uint2* p1 = (uint2*)(base + (((g << 2) + (kk1 & 3)) * 4 + ((kk1 >> 2) << 1)) * 4);
                *p1 = make_uint2(__float_as_uint(s[mt][nt][1]), __float_as_uint(s[mt][nt][3]));
            }

        __syncthreads();   // P visible

        if (c + 1 < 32) ldg_kv(c + 1);   // LDG latency hidden under GEMM2

        // GEMM2: O += P * V  (warp tile: m 64, n 16 of d)
        #pragma unroll
        for (int ks = 0; ks < 8; ks++){
            uint4 af[4]; uint2 bf[2];
            #pragma unroll
            for (int mt = 0; mt < 4; mt++)
                af[mt] = *(const uint4*)(PF + ((((wm*4 + mt)*8 + ks) << 9)) + (lane << 4));
            #pragma unroll
            for (int nt = 0; nt < 2; nt++)
                bf[nt] = *(const uint2*)(VF + ((((wn*2 + nt)*8 + ks) << 8)) + (lane << 3));
            #pragma unroll
            for (int mt = 0; mt < 4; mt++)
                #pragma unroll
                for (int nt = 0; nt < 2; nt++)
                    mma8(o[mt][nt], (const uint32_t*)&af[mt], (const uint32_t*)&bf[nt]);
        }

        __syncthreads();   // GEMM2 done -> KF/VF writable
        if (c + 1 < 32) sts_kv();
        __syncthreads();   // new K/V visible for next GEMM1
    }

    // Reduce l across the 4 wn-warps via SMEM
    if (tt == 0){
        #pragma unroll
        for (int mt = 0; mt < 4; mt++){
            LS[(wm*64 + mt*16 + g) * 4 + wn]     = l0[mt];
            LS[(wm*64 + mt*16 + 8 + g) * 4 + wn] = l1[mt];
        }
    }
    __syncthreads();

    #pragma unroll
    for (int mt = 0; mt < 4; mt++){
        int r0 = wm*64 + mt*16 + g;
        float la = LS[r0*4] + LS[r0*4+1] + LS[r0*4+2] + LS[r0*4+3];
        float lb = LS[(r0+8)*4] + LS[(r0+8)*4+1] + LS[(r0+8)*4+2] + LS[(r0+8)*4+3];
        float ia = 1.f / la, ib = 1.f / lb;
        #pragma unroll
        for (int nt = 0; nt < 2; nt++){
            int col = h*64 + (wn*2 + nt)*8 + (tt << 1);
            *(float2*)(out + (size_t)(qbase + r0) * DM + col) =
                make_float2(o[mt][nt][0] * ia, o[mt][nt][1] * ia);
            *(float2*)(out + (size_t)(qbase + r0 + 8) * DM + col) =
                make_float2(o[mt][nt][2] * ib, o[mt][nt][3] * ib);
        }
    }
}

// ---------------------------------------------------------------------------
extern "C" void kernel_launch(void* const* d_in, const int* in_sizes, int n_in,
                              void* d_out, int out_size)
{
    const float* query = (const float*)d_in[0];
    const float* Wq    = (const float*)d_in[1];
    const float* bq    = (const float*)d_in[2];
    const float* Wk    = (const float*)d_in[3];
    const float* bk    = (const float*)d_in[4];
    const float* Wv    = (const float*)d_in[5];
    const float* bv    = (const float*)d_in[6];
    const float* Wo    = (const float*)d_in[7];
    const float* bo    = (const float*)d_in[8];
    float* out = (float*)d_out;

    float *qb, *kb, *vb, *ab;
    cudaGetSymbolAddress((void**)&qb, g_q);
    cudaGetSymbolAddress((void**)&kb, g_k);
    cudaGetSymbolAddress((void**)&vb, g_v);
    cudaGetSymbolAddress((void**)&ab, g_attn);

    const int GS128 = 16384 + 2 * (128 * 64);   // 32768
    const int GS64  = 16384 + 2 * (64 * 64);    // 24576
    const int ASMEM = 98304 + 2048;             // 100352

    cudaFuncSetAttribute(gemm_mma<128>, cudaFuncAttributeMaxDynamicSharedMemorySize, GS128);
    cudaFuncSetAttribute(gemm_mma<64>,  cudaFuncAttributeMaxDynamicSharedMemorySize, GS64);
    cudaFuncSetAttribute(attn_mma,      cudaFuncAttributeMaxDynamicSharedMemorySize, ASMEM);

    gemm_mma<64> <<<dim3(1, 32), 256, GS64 >>>(query, Wk, bk, kb, MROWS, 64, DM);
    gemm_mma<64> <<<dim3(1, 32), 256, GS64 >>>(query, Wv, bv, vb, MROWS, 64, DM);
    gemm_mma<128><<<dim3(8, 32), 256, GS128>>>(query, Wq, bq, qb, MROWS, DM, DM);

    attn_mma<<<512, 256, ASMEM>>>(qb, kb, vb, ab);

    gemm_mma<128><<<dim3(8, 32), 256, GS128>>>(ab, Wo, bo, out, MROWS, DM, DM);
}

// round 7
// speedup vs baseline: 3.6311x; 2.2236x over previous
#include <cuda_runtime.h>
#include <cstdint>

#define TT 2048
#define DM 1024
#define MROWS 4096

// Scratch (no cudaMalloc allowed)
__device__ float g_q[MROWS*DM];
__device__ float g_k[MROWS*64];
__device__ float g_v[MROWS*64];
__device__ float g_attn[MROWS*DM];

static __device__ __forceinline__ uint32_t f2tf32(float x){
    uint32_t u; asm("cvt.rn.tf32.f32 %0, %1;" : "=r"(u) : "f"(x)); return u;
}
// D += A(m16k8 row) * B(k8n8 col), tf32 inputs, f32 accum
static __device__ __forceinline__ void mma8(float* c, const uint32_t* a, const uint32_t* b){
    asm volatile("mma.sync.aligned.m16n8k8.row.col.f32.tf32.tf32.f32 "
        "{%0,%1,%2,%3}, {%4,%5,%6,%7}, {%8,%9}, {%0,%1,%2,%3};"
        : "+f"(c[0]),"+f"(c[1]),"+f"(c[2]),"+f"(c[3])
        : "r"(a[0]),"r"(a[1]),"r"(a[2]),"r"(a[3]), "r"(b[0]),"r"(b[1]));
}

// A-frag tile (16x8): 512B payload, padded stride 528B (conflict-free scatter)
// B-frag tile (8x8):  256B payload, padded stride 264B (<=2-way scatter)
#define ATS 528
#define BTS 264

// ---------------------------------------------------------------------------
// tf32 mma.sync GEMM + bias: C[M,N] = A[M,K] @ W[K,N] + bias
// Block tile 128 x NT, BK=32, 256 threads, warp grid 2x4, warp tile 64 x NT/4.
// One __syncthreads per chunk; double-buffered frag-layout SMEM.
// ---------------------------------------------------------------------------
template<int NT>
__global__ __launch_bounds__(256, 2) void gemm_mma(
    const float* __restrict__ A, const float* __restrict__ W,
    const float* __restrict__ bias, float* __restrict__ C,
    int M, int N, int K)
{
    extern __shared__ char smem[];
    constexpr int WNT  = NT / 32;          // n-tiles per warp
    constexpr int NTT  = NT / 8;           // B n-tiles per block
    constexpr int ABUF = 32 * ATS;         // 8 mt x 4 ks tiles
    constexpr int BBUF = NTT * 4 * BTS;
    constexpr int NBF4 = NT / 32;          // B float4 loads per thread

    const int tid = threadIdx.x, lane = tid & 31, wid = tid >> 5;
    const int wm = wid >> 2, wn = wid & 3;
    const int bm = blockIdx.y * 128, bn = blockIdx.x * NT;
    const int NC = K >> 5;

    float4 ar[4], br[NBF4];
    auto ldg = [&](int c){
        const int k0 = c << 5;
        #pragma unroll
        for (int i = 0; i < 4; i++){
            int idx = tid + (i << 8); int r = idx >> 3, c4 = (idx & 7) << 2;
            ar[i] = *(const float4*)(A + (size_t)(bm + r) * K + k0 + c4);
        }
        #pragma unroll
        for (int i = 0; i < NBF4; i++){
            int idx = tid + (i << 8); int kk = idx / (NT >> 2), n4 = (idx % (NT >> 2)) << 2;
            br[i] = *(const float4*)(W + (size_t)(k0 + kk) * N + bn + n4);
        }
    };
    auto sts = [&](int buf){
        char* as = smem + buf * ABUF;
        char* bs = smem + 2 * ABUF + buf * BBUF;
        #pragma unroll
        for (int i = 0; i < 4; i++){
            int idx = tid + (i << 8); int r = idx >> 3, c4 = (idx & 7) << 2;
            int mt = r >> 4, rr = r & 15, g = rr & 7, hi = rr >> 3;
            float v[4] = {ar[i].x, ar[i].y, ar[i].z, ar[i].w};
            #pragma unroll
            for (int j = 0; j < 4; j++){
                int cc = c4 + j, ks = cc >> 3, t = cc & 3, chi = (cc & 7) >> 2;
                *(uint32_t*)(as + (mt*4 + ks) * ATS
                    + (((g << 2) + t) * 4 + hi + (chi << 1)) * 4) = f2tf32(v[j]);
            }
        }
        #pragma unroll
        for (int i = 0; i < NBF4; i++){
            int idx = tid + (i << 8); int kk = idx / (NT >> 2), n4 = (idx % (NT >> 2)) << 2;
            int ks = kk >> 3, slot = (kk & 7) >> 2, kb = kk & 3;
            float v[4] = {br[i].x, br[i].y, br[i].z, br[i].w};
            #pragma unroll
            for (int j = 0; j < 4; j++){
                int n = n4 + j, nt = n >> 3;
                *(uint32_t*)(bs + (ks*NTT + nt) * BTS
                    + ((((n & 7) << 2) + kb) * 2 + slot) * 4) = f2tf32(v[j]);
            }
        }
    };

    float acc[4][WNT][4] = {};
    auto comp = [&](int buf){
        const char* as = smem + buf * ABUF;
        const char* bs = smem + 2 * ABUF + buf * BBUF;
        #pragma unroll
        for (int ks = 0; ks < 4; ks++){
            uint4 af[4]; uint2 bf[WNT];
            #pragma unroll
            for (int mt = 0; mt < 4; mt++)
                af[mt] = *(const uint4*)(as + ((wm*4 + mt)*4 + ks) * ATS + lane * 16);
            #pragma unroll
            for (int nt = 0; nt < WNT; nt++)
                bf[nt] = *(const uint2*)(bs + (ks*NTT + wn*WNT + nt) * BTS + lane * 8);
            #pragma unroll
            for (int mt = 0; mt < 4; mt++)
                #pragma unroll
                for (int nt = 0; nt < WNT; nt++)
                    mma8(acc[mt][nt], (const uint32_t*)&af[mt], (const uint32_t*)&bf[nt]);
        }
    };

    ldg(0); sts(0); __syncthreads();
    for (int c = 0; c < NC; c++){
        if (c + 1 < NC) ldg(c + 1);
        comp(c & 1);
        if (c + 1 < NC) sts((c + 1) & 1);
        __syncthreads();
    }

    const int g = lane >> 2, tt = lane & 3;
    #pragma unroll
    for (int mt = 0; mt < 4; mt++){
        int row = bm + wm*64 + mt*16 + g;
        #pragma unroll
        for (int nt = 0; nt < WNT; nt++){
            int col = bn + (wn*WNT + nt)*8 + (tt << 1);
            float b0 = bias[col], b1 = bias[col + 1];
            *(float2*)(C + (size_t)row * N + col) =
                make_float2(acc[mt][nt][0] + b0, acc[mt][nt][1] + b1);
            *(float2*)(C + (size_t)(row + 8) * N + col) =
                make_float2(acc[mt][nt][2] + b0, acc[mt][nt][3] + b1);
        }
    }
}

// ---------------------------------------------------------------------------
// mma.sync flash-MQA v2: one block = (b, h, 128 q-rows), 64-key chunks.
// Each warp owns 16 q-rows end-to-end. S C-frags are reused directly as
// GEMM2 A-frags (register reorder {c0,c2,c1,c3}); V is staged with the
// matching key permutation kn = (kk>>1)+((kk&1)<<2), so P never touches SMEM.
// One __syncthreads per chunk. Unnormalized accumulation; /l at the end.
// SMEM: QF 33792 | KF 2x16896 | VF 2x16896 = 101376 B -> 2 CTA/SM.
// ---------------------------------------------------------------------------
__global__ __launch_bounds__(256, 2) void attn_mma(
    const float* __restrict__ q, const float* __restrict__ k,
    const float* __restrict__ v, float* __restrict__ out)
{
    extern __shared__ char smem[];
    char* QF  = smem;                    // 64 A-tiles (8 warps x 8 ks) x 528B
    char* KF0 = smem + 64 * ATS;         // 64 B-tiles x 264B each buffer
    char* KF1 = KF0 + 64 * BTS;
    char* VF0 = KF1 + 64 * BTS;
    char* VF1 = VF0 + 64 * BTS;

    const int tid = threadIdx.x, lane = tid & 31, wid = tid >> 5;
    const int g = lane >> 2, tt = lane & 3;
    const int bi = blockIdx.x;
    const int qt = bi & 15, h = (bi >> 4) & 15, b = bi >> 8;
    const int qbase = b * TT + qt * 128, kvbase = b * TT;

    // Stage Q (pre-scaled by 1/8) into A-frag layout: tile (mt*8 + ks)
    #pragma unroll
    for (int i = 0; i < 8; i++){
        int idx = tid + (i << 8); int r = idx >> 4, d4 = (idx & 15) << 2;
        float4 a = *(const float4*)(q + (size_t)(qbase + r) * DM + h*64 + d4);
        int mt = r >> 4, rr = r & 15, gg = rr & 7, hi = rr >> 3;
        float vv[4] = {a.x, a.y, a.z, a.w};
        #pragma unroll
        for (int j = 0; j < 4; j++){
            int c = d4 + j, ks = c >> 3, t = c & 3, chi = (c & 7) >> 2;
            *(uint32_t*)(QF + (mt*8 + ks) * ATS
                + (((gg << 2) + t) * 4 + hi + (chi << 1)) * 4) = f2tf32(vv[j] * 0.125f);
        }
    }

    float4 kr[4], vr[4];
    auto ldg_kv = [&](int c){
        const int kc = c << 6;
        #pragma unroll
        for (int i = 0; i < 4; i++){
            int idx = tid + (i << 8); int key = idx >> 4, d4 = (idx & 15) << 2;
            kr[i] = *(const float4*)(k + (size_t)(kvbase + kc + key) * 64 + d4);
            vr[i] = *(const float4*)(v + (size_t)(kvbase + kc + key) * 64 + d4);
        }
    };
    auto sts_kv = [&](char* KF, char* VF){
        #pragma unroll
        for (int i = 0; i < 4; i++){
            int idx = tid + (i << 8); int key = idx >> 4, d4 = (idx & 15) << 2;
            int kk = key & 7;
            int kn = (kk >> 1) + ((kk & 1) << 2);   // GEMM2 key permutation
            float kk4[4] = {kr[i].x, kr[i].y, kr[i].z, kr[i].w};
            float vv4[4] = {vr[i].x, vr[i].y, vr[i].z, vr[i].w};
            #pragma unroll
            for (int j = 0; j < 4; j++){
                int d = d4 + j;
                // K B-frag: tile = keytile*8 + dtile; lane=(key&7)*4+(d&3), slot=(d&7)>>2
                *(uint32_t*)(KF + ((key >> 3)*8 + (d >> 3)) * BTS
                    + (((kk << 2) + (d & 3)) * 2 + ((d & 7) >> 2)) * 4) = f2tf32(kk4[j]);
                // V B-frag (permuted k): tile = keytile*8 + dtile; lane=(d&7)*4+(kn&3), slot=kn>>2
                *(uint32_t*)(VF + ((key >> 3)*8 + (d >> 3)) * BTS
                    + ((((d & 7) << 2) + (kn & 3)) * 2 + (kn >> 2)) * 4) = f2tf32(vv4[j]);
            }
        }
    };

    ldg_kv(0); sts_kv(KF0, VF0); __syncthreads();

    float o[8][4] = {};
    float lg = 0.f, lgh = 0.f;

    for (int c = 0; c < 32; c++){
        char* KF = (c & 1) ? KF1 : KF0;
        char* VF = (c & 1) ? VF1 : VF0;
        if (c + 1 < 32) ldg_kv(c + 1);

        #pragma unroll
        for (int phase = 0; phase < 2; phase++){
            // GEMM1: S(16 x 32 keys) = Q * K^T
            float s[4][4] = {};
            #pragma unroll
            for (int ks = 0; ks < 8; ks++){
                uint4 af = *(const uint4*)(QF + (wid*8 + ks) * ATS + lane * 16);
                #pragma unroll
                for (int nt = 0; nt < 4; nt++){
                    uint2 bf = *(const uint2*)(KF + ((phase*4 + nt)*8 + ks) * BTS + lane * 8);
                    mma8(s[nt], (const uint32_t*)&af, (const uint32_t*)&bf);
                }
            }
            // exp (tf32-rounded so l matches GEMM2 exactly) + partial row sums
            #pragma unroll
            for (int nt = 0; nt < 4; nt++){
                #pragma unroll
                for (int e = 0; e < 4; e++)
                    s[nt][e] = __uint_as_float(f2tf32(__expf(s[nt][e])));
                lg  += s[nt][0] + s[nt][1];
                lgh += s[nt][2] + s[nt][3];
            }
            // GEMM2: O += P * V, P straight from registers (C-frag -> A-frag reorder)
            #pragma unroll
            for (int ksk = 0; ksk < 4; ksk++){
                uint32_t af2[4] = {__float_as_uint(s[ksk][0]), __float_as_uint(s[ksk][2]),
                                   __float_as_uint(s[ksk][1]), __float_as_uint(s[ksk][3])};
                #pragma unroll
                for (int ntd = 0; ntd < 8; ntd++){
                    uint2 bf = *(const uint2*)(VF + ((phase*4 + ksk)*8 + ntd) * BTS + lane * 8);
                    mma8(o[ntd], af2, (const uint32_t*)&bf);
                }
            }
        }

        if (c + 1 < 32) sts_kv((c & 1) ? KF0 : KF1, (c & 1) ? VF0 : VF1);
        __syncthreads();
    }

    // quad reduction of row sums (lanes sharing g)
    lg  += __shfl_xor_sync(~0u, lg, 1);  lg  += __shfl_xor_sync(~0u, lg, 2);
    lgh += __shfl_xor_sync(~0u, lgh, 1); lgh += __shfl_xor_sync(~0u, lgh, 2);
    const float ia = 1.f / lg, ib = 1.f / lgh;

    const int r0 = qbase + wid*16 + g;
    #pragma unroll
    for (int ntd = 0; ntd < 8; ntd++){
        int col = h*64 + ntd*8 + (tt << 1);
        *(float2*)(out + (size_t)r0 * DM + col) =
            make_float2(o[ntd][0] * ia, o[ntd][1] * ia);
        *(float2*)(out + (size_t)(r0 + 8) * DM + col) =
            make_float2(o[ntd][2] * ib, o[ntd][3] * ib);
    }
}

// ---------------------------------------------------------------------------
extern "C" void kernel_launch(void* const* d_in, const int* in_sizes, int n_in,
                              void* d_out, int out_size)
{
    const float* query = (const float*)d_in[0];
    const float* Wq    = (const float*)d_in[1];
    const float* bq    = (const float*)d_in[2];
    const float* Wk    = (const float*)d_in[3];
    const float* bk    = (const float*)d_in[4];
    const float* Wv    = (const float*)d_in[5];
    const float* bv    = (const float*)d_in[6];
    const float* Wo    = (const float*)d_in[7];
    const float* bo    = (const float*)d_in[8];
    float* out = (float*)d_out;

    float *qb, *kb, *vb, *ab;
    cudaGetSymbolAddress((void**)&qb, g_q);
    cudaGetSymbolAddress((void**)&kb, g_k);
    cudaGetSymbolAddress((void**)&vb, g_v);
    cudaGetSymbolAddress((void**)&ab, g_attn);

    const int GS128 = 2*(32*ATS) + 2*(64*BTS);   // 33792 + 33792 = 67584
    const int GS64  = 2*(32*ATS) + 2*(32*BTS);   // 33792 + 16896 = 50688
    const int ASMEM = 64*ATS + 4*(64*BTS);       // 33792 + 67584 = 101376

    cudaFuncSetAttribute(gemm_mma<128>, cudaFuncAttributeMaxDynamicSharedMemorySize, GS128);
    cudaFuncSetAttribute(gemm_mma<64>,  cudaFuncAttributeMaxDynamicSharedMemorySize, GS64);
    cudaFuncSetAttribute(attn_mma,      cudaFuncAttributeMaxDynamicSharedMemorySize, ASMEM);

    gemm_mma<64> <<<dim3(1, 32), 256, GS64 >>>(query, Wk, bk, kb, MROWS, 64, DM);
    gemm_mma<64> <<<dim3(1, 32), 256, GS64 >>>(query, Wv, bv, vb, MROWS, 64, DM);
    gemm_mma<128><<<dim3(8, 32), 256, GS128>>>(query, Wq, bq, qb, MROWS, DM, DM);

    attn_mma<<<512, 256, ASMEM>>>(qb, kb, vb, ab);

    gemm_mma<128><<<dim3(8, 32), 256, GS128>>>(ab, Wo, bo, out, MROWS, DM, DM);
}

// round 8
// speedup vs baseline: 3.8742x; 1.0669x over previous
#include <cuda_runtime.h>
#include <cstdint>

#define TT 2048
#define DM 1024
#define MROWS 4096

// Scratch (no cudaMalloc allowed)
__device__ float g_q[MROWS*DM];
__device__ float g_k[MROWS*64];
__device__ float g_v[MROWS*64];
__device__ float g_attn[MROWS*DM];

static __device__ __forceinline__ uint32_t f2tf32(float x){
    uint32_t u; asm("cvt.rn.tf32.f32 %0, %1;" : "=r"(u) : "f"(x)); return u;
}
// D += A(m16k8 row) * B(k8n8 col), tf32 inputs, f32 accum
static __device__ __forceinline__ void mma8(float* c, const uint32_t* a, const uint32_t* b){
    asm volatile("mma.sync.aligned.m16n8k8.row.col.f32.tf32.tf32.f32 "
        "{%0,%1,%2,%3}, {%4,%5,%6,%7}, {%8,%9}, {%0,%1,%2,%3};"
        : "+f"(c[0]),"+f"(c[1]),"+f"(c[2]),"+f"(c[3])
        : "r"(a[0]),"r"(a[1]),"r"(a[2]),"r"(a[3]), "r"(b[0]),"r"(b[1]));
}

// A-frag tile (16x8): 512B payload, padded stride 528B (conflict-free scatter)
// B-frag tile (8x8):  256B payload, padded stride 264B (<=2-way scatter)
#define ATS 528
#define BTS 264

// ---------------------------------------------------------------------------
// tf32 mma.sync GEMM + bias (unchanged from R7, known-good)
// ---------------------------------------------------------------------------
template<int NT>
__global__ __launch_bounds__(256, 2) void gemm_mma(
    const float* __restrict__ A, const float* __restrict__ W,
    const float* __restrict__ bias, float* __restrict__ C,
    int M, int N, int K)
{
    extern __shared__ char smem[];
    constexpr int WNT  = NT / 32;
    constexpr int NTT  = NT / 8;
    constexpr int ABUF = 32 * ATS;
    constexpr int BBUF = NTT * 4 * BTS;
    constexpr int NBF4 = NT / 32;

    const int tid = threadIdx.x, lane = tid & 31, wid = tid >> 5;
    const int wm = wid >> 2, wn = wid & 3;
    const int bm = blockIdx.y * 128, bn = blockIdx.x * NT;
    const int NC = K >> 5;

    float4 ar[4], br[NBF4];
    auto ldg = [&](int c){
        const int k0 = c << 5;
        #pragma unroll
        for (int i = 0; i < 4; i++){
            int idx = tid + (i << 8); int r = idx >> 3, c4 = (idx & 7) << 2;
            ar[i] = *(const float4*)(A + (size_t)(bm + r) * K + k0 + c4);
        }
        #pragma unroll
        for (int i = 0; i < NBF4; i++){
            int idx = tid + (i << 8); int kk = idx / (NT >> 2), n4 = (idx % (NT >> 2)) << 2;
            br[i] = *(const float4*)(W + (size_t)(k0 + kk) * N + bn + n4);
        }
    };
    auto sts = [&](int buf){
        char* as = smem + buf * ABUF;
        char* bs = smem + 2 * ABUF + buf * BBUF;
        #pragma unroll
        for (int i = 0; i < 4; i++){
            int idx = tid + (i << 8); int r = idx >> 3, c4 = (idx & 7) << 2;
            int mt = r >> 4, rr = r & 15, g = rr & 7, hi = rr >> 3;
            float v[4] = {ar[i].x, ar[i].y, ar[i].z, ar[i].w};
            #pragma unroll
            for (int j = 0; j < 4; j++){
                int cc = c4 + j, ks = cc >> 3, t = cc & 3, chi = (cc & 7) >> 2;
                *(uint32_t*)(as + (mt*4 + ks) * ATS
                    + (((g << 2) + t) * 4 + hi + (chi << 1)) * 4) = f2tf32(v[j]);
            }
        }
        #pragma unroll
        for (int i = 0; i < NBF4; i++){
            int idx = tid + (i << 8); int kk = idx / (NT >> 2), n4 = (idx % (NT >> 2)) << 2;
            int ks = kk >> 3, slot = (kk & 7) >> 2, kb = kk & 3;
            float v[4] = {br[i].x, br[i].y, br[i].z, br[i].w};
            #pragma unroll
            for (int j = 0; j < 4; j++){
                int n = n4 + j, nt = n >> 3;
                *(uint32_t*)(bs + (ks*NTT + nt) * BTS
                    + ((((n & 7) << 2) + kb) * 2 + slot) * 4) = f2tf32(v[j]);
            }
        }
    };

    float acc[4][WNT][4] = {};
    auto comp = [&](int buf){
        const char* as = smem + buf * ABUF;
        const char* bs = smem + 2 * ABUF + buf * BBUF;
        #pragma unroll
        for (int ks = 0; ks < 4; ks++){
            uint4 af[4]; uint2 bf[WNT];
            #pragma unroll
            for (int mt = 0; mt < 4; mt++)
                af[mt] = *(const uint4*)(as + ((wm*4 + mt)*4 + ks) * ATS + lane * 16);
            #pragma unroll
            for (int nt = 0; nt < WNT; nt++)
                bf[nt] = *(const uint2*)(bs + (ks*NTT + wn*WNT + nt) * BTS + lane * 8);
            #pragma unroll
            for (int mt = 0; mt < 4; mt++)
                #pragma unroll
                for (int nt = 0; nt < WNT; nt++)
                    mma8(acc[mt][nt], (const uint32_t*)&af[mt], (const uint32_t*)&bf[nt]);
        }
    };

    ldg(0); sts(0); __syncthreads();
    for (int c = 0; c < NC; c++){
        if (c + 1 < NC) ldg(c + 1);
        comp(c & 1);
        if (c + 1 < NC) sts((c + 1) & 1);
        __syncthreads();
    }

    const int g = lane >> 2, tt = lane & 3;
    #pragma unroll
    for (int mt = 0; mt < 4; mt++){
        int row = bm + wm*64 + mt*16 + g;
        #pragma unroll
        for (int nt = 0; nt < WNT; nt++){
            int col = bn + (wn*WNT + nt)*8 + (tt << 1);
            float b0 = bias[col], b1 = bias[col + 1];
            *(float2*)(C + (size_t)row * N + col) =
                make_float2(acc[mt][nt][0] + b0, acc[mt][nt][1] + b1);
            *(float2*)(C + (size_t)(row + 8) * N + col) =
                make_float2(acc[mt][nt][2] + b0, acc[mt][nt][3] + b1);
        }
    }
}

// ---------------------------------------------------------------------------
// mma.sync flash-MQA v3: one block = (b, h, 128 q-rows), 64-key chunks.
// Warp owns m=32 (two 16-row tiles) -> every B-frag feeds 2 MMAs (bytes/MMA
// 10 -> 6). Keys split across warp-groups: warps 0-3 keys [0,32), warps 4-7
// keys [32,64) of each chunk; partial O/l accumulated over all chunks, summed
// once at the end through SMEM (group 1 -> dead KF region).
// P stays in registers (C-frag -> A-frag reorder + V key permutation).
// ---------------------------------------------------------------------------
__global__ __launch_bounds__(256, 2) void attn_mma(
    const float* __restrict__ q, const float* __restrict__ k,
    const float* __restrict__ v, float* __restrict__ out)
{
    extern __shared__ char smem[];
    char* QF  = smem;                    // 64 A-tiles (8 mt x 8 ks) x 528B
    char* KF0 = smem + 64 * ATS;
    char* KF1 = KF0 + 64 * BTS;
    char* VF0 = KF1 + 64 * BTS;
    char* VF1 = VF0 + 64 * BTS;
    float* OX = (float*)KF0;             // [128][66] exchange (after loop)
    float* LX = (float*)VF0;             // [128]     exchange (after loop)

    const int tid = threadIdx.x, lane = tid & 31, wid = tid >> 5;
    const int g = lane >> 2, tt = lane & 3;
    const int grp = wid >> 2;            // key half
    const int mq  = wid & 3;             // row quarter (32 rows)
    const int bi = blockIdx.x;
    const int qt = bi & 15, h = (bi >> 4) & 15, b = bi >> 8;
    const int qbase = b * TT + qt * 128, kvbase = b * TT;

    // Stage Q (pre-scaled by 1/8) into A-frag layout: tile (mt*8 + ks)
    #pragma unroll
    for (int i = 0; i < 8; i++){
        int idx = tid + (i << 8); int r = idx >> 4, d4 = (idx & 15) << 2;
        float4 a = *(const float4*)(q + (size_t)(qbase + r) * DM + h*64 + d4);
        int mt = r >> 4, rr = r & 15, gg = rr & 7, hi = rr >> 3;
        float vv[4] = {a.x, a.y, a.z, a.w};
        #pragma unroll
        for (int j = 0; j < 4; j++){
            int c = d4 + j, ks = c >> 3, t = c & 3, chi = (c & 7) >> 2;
            *(uint32_t*)(QF + (mt*8 + ks) * ATS
                + (((gg << 2) + t) * 4 + hi + (chi << 1)) * 4) = f2tf32(vv[j] * 0.125f);
        }
    }

    float4 kr[4], vr[4];
    auto ldg_k = [&](int c){
        const int kc = c << 6;
        #pragma unroll
        for (int i = 0; i < 4; i++){
            int idx = tid + (i << 8); int key = idx >> 4, d4 = (idx & 15) << 2;
            kr[i] = *(const float4*)(k + (size_t)(kvbase + kc + key) * 64 + d4);
        }
    };
    auto ldg_v = [&](int c){
        const int kc = c << 6;
        #pragma unroll
        for (int i = 0; i < 4; i++){
            int idx = tid + (i << 8); int key = idx >> 4, d4 = (idx & 15) << 2;
            vr[i] = *(const float4*)(v + (size_t)(kvbase + kc + key) * 64 + d4);
        }
    };
    auto sts_k = [&](char* KF){
        #pragma unroll
        for (int i = 0; i < 4; i++){
            int idx = tid + (i << 8); int key = idx >> 4, d4 = (idx & 15) << 2;
            int kk = key & 7;
            float kk4[4] = {kr[i].x, kr[i].y, kr[i].z, kr[i].w};
            #pragma unroll
            for (int j = 0; j < 4; j++){
                int d = d4 + j;
                *(uint32_t*)(KF + ((key >> 3)*8 + (d >> 3)) * BTS
                    + (((kk << 2) + (d & 3)) * 2 + ((d & 7) >> 2)) * 4) = f2tf32(kk4[j]);
            }
        }
    };
    auto sts_v = [&](char* VF){
        #pragma unroll
        for (int i = 0; i < 4; i++){
            int idx = tid + (i << 8); int key = idx >> 4, d4 = (idx & 15) << 2;
            int kk = key & 7;
            int kn = (kk >> 1) + ((kk & 1) << 2);   // GEMM2 key permutation
            float vv4[4] = {vr[i].x, vr[i].y, vr[i].z, vr[i].w};
            #pragma unroll
            for (int j = 0; j < 4; j++){
                int d = d4 + j;
                *(uint32_t*)(VF + ((key >> 3)*8 + (d >> 3)) * BTS
                    + ((((d & 7) << 2) + (kn & 3)) * 2 + (kn >> 2)) * 4) = f2tf32(vv4[j]);
            }
        }
    };

    ldg_k(0); ldg_v(0); sts_k(KF0); sts_v(VF0); __syncthreads();

    float o[2][8][4] = {};
    float l[2][2] = {};

    for (int c = 0; c < 32; c++){
        char* KF = (c & 1) ? KF1 : KF0;
        char* VF = (c & 1) ? VF1 : VF0;

        // GEMM1: S(32 x 32 keys) = Q * K^T ; B-frag shared by both m-tiles
        float s[2][4][4] = {};
        #pragma unroll
        for (int ks = 0; ks < 8; ks++){
            uint4 af0 = *(const uint4*)(QF + ((mq*2 + 0)*8 + ks) * ATS + lane * 16);
            uint4 af1 = *(const uint4*)(QF + ((mq*2 + 1)*8 + ks) * ATS + lane * 16);
            #pragma unroll
            for (int nt = 0; nt < 4; nt++){
                uint2 bf = *(const uint2*)(KF + ((grp*4 + nt)*8 + ks) * BTS + lane * 8);
                mma8(s[0][nt], (const uint32_t*)&af0, (const uint32_t*)&bf);
                mma8(s[1][nt], (const uint32_t*)&af1, (const uint32_t*)&bf);
            }
        }

        // exp (tf32-rounded so l matches GEMM2 exactly) + partial row sums
        #pragma unroll
        for (int m = 0; m < 2; m++)
            #pragma unroll
            for (int nt = 0; nt < 4; nt++){
                #pragma unroll
                for (int e = 0; e < 4; e++)
                    s[m][nt][e] = __uint_as_float(f2tf32(__expf(s[m][nt][e])));
                l[m][0] += s[m][nt][0] + s[m][nt][1];
                l[m][1] += s[m][nt][2] + s[m][nt][3];
            }

        if (c + 1 < 32) ldg_k(c + 1);   // K-load latency hidden under GEMM2

        // GEMM2: O += P * V ; P from registers, B-frag shared by both m-tiles
        #pragma unroll
        for (int ksk = 0; ksk < 4; ksk++){
            uint32_t a0[4] = {__float_as_uint(s[0][ksk][0]), __float_as_uint(s[0][ksk][2]),
                              __float_as_uint(s[0][ksk][1]), __float_as_uint(s[0][ksk][3])};
            uint32_t a1[4] = {__float_as_uint(s[1][ksk][0]), __float_as_uint(s[1][ksk][2]),
                              __float_as_uint(s[1][ksk][1]), __float_as_uint(s[1][ksk][3])};
            #pragma unroll
            for (int ntd = 0; ntd < 8; ntd++){
                uint2 bf = *(const uint2*)(VF + ((grp*4 + ksk)*8 + ntd) * BTS + lane * 8);
                mma8(o[0][ntd], a0, (const uint32_t*)&bf);
                mma8(o[1][ntd], a1, (const uint32_t*)&bf);
            }
        }

        if (c + 1 < 32){
            char* KFn = (c & 1) ? KF0 : KF1;
            char* VFn = (c & 1) ? VF0 : VF1;
            sts_k(KFn);
            ldg_v(c + 1);
            sts_v(VFn);
        }
        __syncthreads();
    }

    // quad reduction of partial row sums (lanes sharing g)
    #pragma unroll
    for (int m = 0; m < 2; m++){
        l[m][0] += __shfl_xor_sync(~0u, l[m][0], 1);
        l[m][0] += __shfl_xor_sync(~0u, l[m][0], 2);
        l[m][1] += __shfl_xor_sync(~0u, l[m][1], 1);
        l[m][1] += __shfl_xor_sync(~0u, l[m][1], 2);
    }

    // cross-group combine: group 1 dumps partial O/l into (dead) KF/VF space
    if (grp == 1){
        #pragma unroll
        for (int mt = 0; mt < 2; mt++){
            int r = mq*32 + mt*16 + g;
            #pragma unroll
            for (int ntd = 0; ntd < 8; ntd++){
                int cw = ntd*8 + (tt << 1);
                *(float2*)&OX[r*66 + cw]       = make_float2(o[mt][ntd][0], o[mt][ntd][1]);
                *(float2*)&OX[(r+8)*66 + cw]   = make_float2(o[mt][ntd][2], o[mt][ntd][3]);
            }
            if (tt == 0){ LX[r] = l[mt][0]; LX[r+8] = l[mt][1]; }
        }
    }
    __syncthreads();
    if (grp == 0){
        #pragma unroll
        for (int mt = 0; mt < 2; mt++){
            int r = mq*32 + mt*16 + g;
            float ia = 1.f / (l[mt][0] + LX[r]);
            float ib = 1.f / (l[mt][1] + LX[r+8]);
            #pragma unroll
            for (int ntd = 0; ntd < 8; ntd++){
                int cw = ntd*8 + (tt << 1);
                float2 pa = *(const float2*)&OX[r*66 + cw];
                float2 pb = *(const float2*)&OX[(r+8)*66 + cw];
                int col = h*64 + cw;
                *(float2*)(out + (size_t)(qbase + r) * DM + col) =
                    make_float2((o[mt][ntd][0] + pa.x) * ia, (o[mt][ntd][1] + pa.y) * ia);
                *(float2*)(out + (size_t)(qbase + r + 8) * DM + col) =
                    make_float2((o[mt][ntd][2] + pb.x) * ib, (o[mt][ntd][3] + pb.y) * ib);
            }
        }
    }
}

// ---------------------------------------------------------------------------
extern "C" void kernel_launch(void* const* d_in, const int* in_sizes, int n_in,
                              void* d_out, int out_size)
{
    const float* query = (const float*)d_in[0];
    const float* Wq    = (const float*)d_in[1];
    const float* bq    = (const float*)d_in[2];
    const float* Wk    = (const float*)d_in[3];
    const float* bk    = (const float*)d_in[4];
    const float* Wv    = (const float*)d_in[5];
    const float* bv    = (const float*)d_in[6];
    const float* Wo    = (const float*)d_in[7];
    const float* bo    = (const float*)d_in[8];
    float* out = (float*)d_out;

    float *qb, *kb, *vb, *ab;
    cudaGetSymbolAddress((void**)&qb, g_q);
    cudaGetSymbolAddress((void**)&kb, g_k);
    cudaGetSymbolAddress((void**)&vb, g_v);
    cudaGetSymbolAddress((void**)&ab, g_attn);

    const int GS128 = 2*(32*ATS) + 2*(64*BTS);   // 67584
    const int GS64  = 2*(32*ATS) + 2*(32*BTS);   // 50688
    const int ASMEM = 64*ATS + 4*(64*BTS);       // 101376

    cudaFuncSetAttribute(gemm_mma<128>, cudaFuncAttributeMaxDynamicSharedMemorySize, GS128);
    cudaFuncSetAttribute(gemm_mma<64>,  cudaFuncAttributeMaxDynamicSharedMemorySize, GS64);
    cudaFuncSetAttribute(attn_mma,      cudaFuncAttributeMaxDynamicSharedMemorySize, ASMEM);

    gemm_mma<64> <<<dim3(1, 32), 256, GS64 >>>(query, Wk, bk, kb, MROWS, 64, DM);
    gemm_mma<64> <<<dim3(1, 32), 256, GS64 >>>(query, Wv, bv, vb, MROWS, 64, DM);
    gemm_mma<128><<<dim3(8, 32), 256, GS128>>>(query, Wq, bq, qb, MROWS, DM, DM);

    attn_mma<<<512, 256, ASMEM>>>(qb, kb, vb, ab);

    gemm_mma<128><<<dim3(8, 32), 256, GS128>>>(ab, Wo, bo, out, MROWS, DM, DM);
}